// round 4
// baseline (speedup 1.0000x reference)
#include <cuda_runtime.h>
#include <cstdint>

#define INV_SQRT_E 0.08838834764831843f

__device__ float g_G [32ull*1024*256];   // interleaved: [2h]=ek, [2h+1]=ek*v
__device__ float g_Q [32ull*1024*128];   // sigmoid(q)
__device__ float g_AFT[32ull*1024*128];

__device__ __forceinline__ float tf32r(float x){
  uint32_t u; asm("cvt.rna.tf32.f32 %0,%1;":"=r"(u):"f"(x)); return __uint_as_float(u);
}
__device__ __forceinline__ void mma8(float* c, const float* a, const float* b){
  asm volatile("mma.sync.aligned.m16n8k8.row.col.f32.tf32.tf32.f32 "
    "{%0,%1,%2,%3},{%4,%5,%6,%7},{%8,%9},{%0,%1,%2,%3};"
    : "+f"(c[0]),"+f"(c[1]),"+f"(c[2]),"+f"(c[3])
    : "r"(__float_as_uint(a[0])),"r"(__float_as_uint(a[1])),
      "r"(__float_as_uint(a[2])),"r"(__float_as_uint(a[3])),
      "r"(__float_as_uint(b[0])),"r"(__float_as_uint(b[1])));
}
// 128x32 tile (row stride ld) -> smem [r*pad+c], tf32-rounded
__device__ __forceinline__ void ld128x32(float* s, const float* g, int ld, int pad, int t){
#pragma unroll
  for(int j=0;j<4;j++){ int i4=j*256+t; int r=i4>>3, c=(i4&7)*4;
    float4 v=*(const float4*)(g + (size_t)r*ld + c);
    v.x=tf32r(v.x); v.y=tf32r(v.y); v.z=tf32r(v.z); v.w=tf32r(v.w);
    *(float4*)(s + r*pad + c)=v; }
}
// 128x16 tile -> smem
__device__ __forceinline__ void ld128x16(float* s, const float* g, int ld, int pad, int t){
#pragma unroll
  for(int j=0;j<2;j++){ int i4=j*256+t; int r=i4>>2, c=(i4&3)*4;
    float4 v=*(const float4*)(g + (size_t)r*ld + c);
    v.x=tf32r(v.x); v.y=tf32r(v.y); v.z=tf32r(v.z); v.w=tf32r(v.w);
    *(float4*)(s + r*pad + c)=v; }
}
// 32x128 tile -> smem
__device__ __forceinline__ void ld32x128(float* s, const float* g, int ld, int pad, int t){
#pragma unroll
  for(int j=0;j<4;j++){ int i4=j*256+t; int r=i4>>5, c=(i4&31)*4;
    float4 v=*(const float4*)(g + (size_t)r*ld + c);
    v.x=tf32r(v.x); v.y=tf32r(v.y); v.z=tf32r(v.z); v.w=tf32r(v.w);
    *(float4*)(s + r*pad + c)=v; }
}

// ---- K_q: g_Q = sigmoid(q1@W1 + q2@W2 + last@WL[0:128] + load*WL[128] + left*WL[129])
__global__ void __launch_bounds__(256,1) k_q(
 const float* __restrict__ q1,const float* __restrict__ q2,const float* __restrict__ ql,
 const float* __restrict__ load,const float* __restrict__ left,
 const float* __restrict__ W1,const float* __restrict__ W2,const float* __restrict__ WL){
 __shared__ float sA[128*36], sB[32*136];
 int t=threadIdx.x, lane=t&31, w=t>>5, wm=w>>2, wn=w&3, g=lane>>2, t4=lane&3;
 int b=blockIdx.y, p0=blockIdx.x*128;
 float acc[4][4][4]={};
 const float* srcs[3]={q1,q2,ql};
 const float* Ws[3]={W1,W2,WL};
 for(int c=0;c<12;c++){
   int s=c>>2, kc=(c&3)*32;
   __syncthreads();
   ld128x32(sA, srcs[s] + ((size_t)(b*1024+p0))*128 + kc, 128, 36, t);
   ld32x128(sB, Ws[s] + (size_t)kc*128, 128, 136, t);
   __syncthreads();
#pragma unroll
   for(int kk=0;kk<32;kk+=8){
     float a[4][4], bb[4][2];
#pragma unroll
     for(int mi=0;mi<4;mi++){ int r=(wm*64+mi*16+g)*36+kk+t4;
       a[mi][0]=sA[r]; a[mi][1]=sA[r+8*36]; a[mi][2]=sA[r+4]; a[mi][3]=sA[r+8*36+4]; }
#pragma unroll
     for(int ni=0;ni<4;ni++){ int cc=wn*32+ni*8+g;
       bb[ni][0]=sB[(kk+t4)*136+cc]; bb[ni][1]=sB[(kk+4+t4)*136+cc]; }
#pragma unroll
     for(int mi=0;mi<4;mi++)
#pragma unroll
       for(int ni=0;ni<4;ni++) mma8(acc[mi][ni], a[mi], bb[ni]);
   }
 }
#pragma unroll
 for(int mi=0;mi<4;mi++)
#pragma unroll
  for(int half=0;half<2;half++){
   int r=wm*64+mi*16+g+half*8;
   size_t pr=(size_t)(b*1024+p0+r);
   float ld=load[pr], lf=left[pr];
#pragma unroll
   for(int ni=0;ni<4;ni++){
     int h=wn*32+ni*8+t4*2;
     float v0=acc[mi][ni][half*2+0]+ld*WL[128*128+h]  +lf*WL[129*128+h];
     float v1=acc[mi][ni][half*2+1]+ld*WL[128*128+h+1]+lf*WL[129*128+h+1];
     float2 o; o.x=1.f/(1.f+__expf(-v0)); o.y=1.f/(1.f+__expf(-v1));
     *(float2*)&g_Q[pr*128+h]=o;
   }
  }
}

// ---- K_kv (fused): k=nodes@Wk, v=nodes@Wv; g_G[bn][2h]=tf32(exp(k)), [2h+1]=tf32(exp(k)*v)
// Warp column map pairs (h, h+128) in the same thread: ni<4 -> k cols, ni>=4 -> v cols.
__global__ void __launch_bounds__(256,1) k_kv(const float* __restrict__ nodes,
 const float* __restrict__ Wk,const float* __restrict__ Wv){
 __shared__ float sA[128*20], sB[16*264];
 int t=threadIdx.x, lane=t&31, w=t>>5, wm=w>>2, wn=w&3, g=lane>>2, t4=lane&3;
 int b=blockIdx.y, n0=blockIdx.x*128;
 float acc[4][8][4]={};
 for(int c=0;c<8;c++){
   int kc=c*16;
   __syncthreads();
   ld128x16(sA, nodes + ((size_t)(b*1024+n0))*128 + kc, 128, 20, t);
#pragma unroll
   for(int j=0;j<4;j++){ int i4=j*256+t; int r=i4>>6, cc=(i4&63)*4;
     const float* src = (cc<128)? (Wk+(size_t)(kc+r)*128+cc) : (Wv+(size_t)(kc+r)*128+cc-128);
     float4 v=*(const float4*)src;
     v.x=tf32r(v.x); v.y=tf32r(v.y); v.z=tf32r(v.z); v.w=tf32r(v.w);
     *(float4*)(sB + r*264 + cc)=v; }
   __syncthreads();
#pragma unroll
   for(int kk=0;kk<16;kk+=8){
     float a[4][4], bb[8][2];
#pragma unroll
     for(int mi=0;mi<4;mi++){ int r=(wm*64+mi*16+g)*20+kk+t4;
       a[mi][0]=sA[r]; a[mi][1]=sA[r+8*20]; a[mi][2]=sA[r+4]; a[mi][3]=sA[r+8*20+4]; }
#pragma unroll
     for(int ni=0;ni<8;ni++){
       int cc=((ni<4)? (wn*32+ni*8) : (128+wn*32+(ni-4)*8))+g;
       bb[ni][0]=sB[(kk+t4)*264+cc]; bb[ni][1]=sB[(kk+4+t4)*264+cc]; }
#pragma unroll
     for(int mi=0;mi<4;mi++)
#pragma unroll
       for(int ni=0;ni<8;ni++) mma8(acc[mi][ni], a[mi], bb[ni]);
   }
 }
#pragma unroll
 for(int mi=0;mi<4;mi++)
#pragma unroll
  for(int half=0;half<2;half++){
   int r=wm*64+mi*16+g+half*8;
   size_t bn=(size_t)(b*1024+n0+r);
#pragma unroll
   for(int ni=0;ni<4;ni++){
     int h=wn*32+ni*8+t4*2;
     float k0=acc[mi][ni][half*2],   k1=acc[mi][ni][half*2+1];
     float v0=acc[mi][ni+4][half*2], v1=acc[mi][ni+4][half*2+1];
     float e0=__expf(k0), e1=__expf(k1);
     float4 o; o.x=tf32r(e0); o.y=tf32r(e0*v0); o.z=tf32r(e1); o.w=tf32r(e1*v1);
     *(float4*)&g_G[bn*256 + 2*h]=o;
   }
  }
}

// ---- K_aft: W=exp(mask-lsa*d); [den|num]=W@G; AFT = qsig*num/(den+eps)
__global__ void __launch_bounds__(256,1) k_aft(const float* __restrict__ dist,
 const float* __restrict__ mask,const float* __restrict__ ls,const float* __restrict__ aa){
 __shared__ float sW[128*20], sG[16*264];
 int t=threadIdx.x, lane=t&31, w=t>>5, wm=w>>2, wn=w&3, g=lane>>2, t4=lane&3;
 int b=blockIdx.y, p0=blockIdx.x*128;
 float lsa=ls[0]*aa[0];
 float acc[4][8][4]={};
 for(int c=0;c<64;c++){
   int n0c=c*16;
   __syncthreads();
   { int p=t>>1, off=(t&1)*8;
     size_t base=((size_t)(b*1024+p0+p))*1024 + n0c + off;
     float4 d0=*(const float4*)(dist+base), d1=*(const float4*)(dist+base+4);
     float4 m0=*(const float4*)(mask+base), m1=*(const float4*)(mask+base+4);
     float* sw=sW+p*20+off;
     sw[0]=tf32r(__expf(m0.x-lsa*d0.x)); sw[1]=tf32r(__expf(m0.y-lsa*d0.y));
     sw[2]=tf32r(__expf(m0.z-lsa*d0.z)); sw[3]=tf32r(__expf(m0.w-lsa*d0.w));
     sw[4]=tf32r(__expf(m1.x-lsa*d1.x)); sw[5]=tf32r(__expf(m1.y-lsa*d1.y));
     sw[6]=tf32r(__expf(m1.z-lsa*d1.z)); sw[7]=tf32r(__expf(m1.w-lsa*d1.w));
   }
#pragma unroll
   for(int j=0;j<4;j++){ int i4=j*256+t; int r=i4>>6, cc=(i4&63)*4;
     *(float4*)(sG+r*264+cc)=*(const float4*)(((const float*)g_G)+((size_t)(b*1024+n0c+r))*256+cc); }
   __syncthreads();
#pragma unroll
   for(int kk=0;kk<16;kk+=8){
     float a[4][4], bb[8][2];
#pragma unroll
     for(int mi=0;mi<4;mi++){ int r=(wm*64+mi*16+g)*20+kk+t4;
       a[mi][0]=sW[r]; a[mi][1]=sW[r+8*20]; a[mi][2]=sW[r+4]; a[mi][3]=sW[r+8*20+4]; }
#pragma unroll
     for(int ni=0;ni<8;ni++){ int cc=wn*64+ni*8+g;
       bb[ni][0]=sG[(kk+t4)*264+cc]; bb[ni][1]=sG[(kk+4+t4)*264+cc]; }
#pragma unroll
     for(int mi=0;mi<4;mi++)
#pragma unroll
       for(int ni=0;ni<8;ni++) mma8(acc[mi][ni], a[mi], bb[ni]);
   }
 }
#pragma unroll
 for(int mi=0;mi<4;mi++)
#pragma unroll
  for(int half=0;half<2;half++){
   int r=wm*64+mi*16+g+half*8;
#pragma unroll
   for(int ni=0;ni<8;ni++){
     int h=wn*32+ni*4+t4;
     float den=acc[mi][ni][half*2], num=acc[mi][ni][half*2+1];
     size_t idx=(size_t)(b*1024+p0+r)*128+h;
     g_AFT[idx]=tf32r(g_Q[idx]*num/(den+1e-20f));
   }
  }
}

// ---- K_score: score=AFT@nodes^T; probs=softmax(10*tanh(score/sqrtE - lsp*d)+mask)
__global__ void __launch_bounds__(256,1) k_score(const float* __restrict__ nodes,
 const float* __restrict__ dist,const float* __restrict__ mask,
 const float* __restrict__ ls,const float* __restrict__ pa,float* __restrict__ out){
 __shared__ float sA[128*36], sB[128*36], sSum[128];
 int t=threadIdx.x, lane=t&31, w=t>>5, wm=w>>2, wn=w&3, g=lane>>2, t4=lane&3;
 int b=blockIdx.y, p0=blockIdx.x*128;
 if(t<128) sSum[t]=0.f;
 float lsp=ls[0]*pa[0];
 float rs[8]={};
 for(int nc=0;nc<8;nc++){
   int n0=nc*128;
   float acc[4][4][4]={};
   for(int kc=0;kc<4;kc++){
     __syncthreads();
     ld128x32(sA, ((const float*)g_AFT) + ((size_t)(b*1024+p0))*128 + kc*32, 128, 36, t);
     ld128x32(sB, nodes + ((size_t)(b*1024+n0))*128 + kc*32, 128, 36, t);
     __syncthreads();
#pragma unroll
     for(int kk=0;kk<32;kk+=8){
       float a[4][4], bb[4][2];
#pragma unroll
       for(int mi=0;mi<4;mi++){ int r=(wm*64+mi*16+g)*36+kk+t4;
         a[mi][0]=sA[r]; a[mi][1]=sA[r+8*36]; a[mi][2]=sA[r+4]; a[mi][3]=sA[r+8*36+4]; }
#pragma unroll
       for(int ni=0;ni<4;ni++){ int n=(wn*32+ni*8+g)*36+kk+t4;
         bb[ni][0]=sB[n]; bb[ni][1]=sB[n+4]; }
#pragma unroll
       for(int mi=0;mi<4;mi++)
#pragma unroll
         for(int ni=0;ni<4;ni++) mma8(acc[mi][ni], a[mi], bb[ni]);
     }
   }
#pragma unroll
   for(int mi=0;mi<4;mi++)
#pragma unroll
    for(int half=0;half<2;half++){
     int r=wm*64+mi*16+g+half*8;
     size_t rb=((size_t)(b*1024+p0+r))*1024;
#pragma unroll
     for(int ni=0;ni<4;ni++){
       int n=n0+wn*32+ni*8+t4*2;
       float2 d2=*(const float2*)(dist+rb+n);
       float2 m2=*(const float2*)(mask+rb+n);
       float x0=acc[mi][ni][half*2]*INV_SQRT_E - lsp*d2.x;
       float x1=acc[mi][ni][half*2+1]*INV_SQRT_E - lsp*d2.y;
       float e0=__expf(10.f*(1.f-2.f/(__expf(2.f*x0)+1.f))+m2.x);
       float e1=__expf(10.f*(1.f-2.f/(__expf(2.f*x1)+1.f))+m2.y);
       float2 o; o.x=e0; o.y=e1;
       *(float2*)(out+rb+n)=o;
       rs[mi*2+half]+=e0+e1;
     }
    }
 }
#pragma unroll
 for(int i=0;i<8;i++){
   float v=rs[i];
   v+=__shfl_xor_sync(0xffffffffu,v,1);
   v+=__shfl_xor_sync(0xffffffffu,v,2);
   if(t4==0) atomicAdd(&sSum[wm*64+(i>>1)*16+g+(i&1)*8], v);
 }
 __syncthreads();
 float* ob=out+((size_t)(b*1024+p0))*1024;
 for(int j=0;j<128;j++){
   float inv=1.f/sSum[j];
   float4 v=*(float4*)(ob+(size_t)j*1024+t*4);
   v.x*=inv; v.y*=inv; v.z*=inv; v.w*=inv;
   *(float4*)(ob+(size_t)j*1024+t*4)=v;
 }
}

extern "C" void kernel_launch(void* const* d_in, const int*, int, void* d_out, int){
  const float* nodes=(const float*)d_in[0];
  const float* q1  =(const float*)d_in[1];
  const float* q2  =(const float*)d_in[2];
  const float* qln =(const float*)d_in[3];
  const float* load=(const float*)d_in[4];
  const float* left=(const float*)d_in[5];
  const float* dist=(const float*)d_in[6];
  const float* ls  =(const float*)d_in[7];
  const float* mask=(const float*)d_in[8];
  const float* Wq1 =(const float*)d_in[9];
  const float* Wq2 =(const float*)d_in[10];
  const float* WqL =(const float*)d_in[11];
  const float* Wk  =(const float*)d_in[12];
  const float* Wv  =(const float*)d_in[13];
  const float* aa  =(const float*)d_in[14];
  const float* pa  =(const float*)d_in[15];
  float* out=(float*)d_out;
  k_q    <<<dim3(8,32),256>>>(q1,q2,qln,load,left,Wq1,Wq2,WqL);
  k_kv   <<<dim3(8,32),256>>>(nodes,Wk,Wv);
  k_aft  <<<dim3(8,32),256>>>(dist,mask,ls,aa);
  k_score<<<dim3(8,32),256>>>(nodes,dist,mask,ls,pa,out);
}

// round 5
// speedup vs baseline: 1.1591x; 1.1591x over previous
#include <cuda_runtime.h>
#include <cstdint>

#define INV_SQRT_E 0.08838834764831843f

__device__ float g_G [32ull*1024*256];   // interleaved: [2h]=ek, [2h+1]=ek*v
__device__ float g_Q [32ull*1024*128];   // sigmoid(q)
__device__ float g_AFT[32ull*1024*128];
__device__ float g_PD [2ull*32768*256];  // partial [den|num] interleaved, 2 n-slices
__device__ float g_psum[32768ull*4];     // per-row softmax partial sums, 4 n-slots

__device__ __forceinline__ float tf32r(float x){
  uint32_t u; asm("cvt.rna.tf32.f32 %0,%1;":"=r"(u):"f"(x)); return __uint_as_float(u);
}
__device__ __forceinline__ void mma8(float* c, const float* a, const float* b){
  asm volatile("mma.sync.aligned.m16n8k8.row.col.f32.tf32.tf32.f32 "
    "{%0,%1,%2,%3},{%4,%5,%6,%7},{%8,%9},{%0,%1,%2,%3};"
    : "+f"(c[0]),"+f"(c[1]),"+f"(c[2]),"+f"(c[3])
    : "r"(__float_as_uint(a[0])),"r"(__float_as_uint(a[1])),
      "r"(__float_as_uint(a[2])),"r"(__float_as_uint(a[3])),
      "r"(__float_as_uint(b[0])),"r"(__float_as_uint(b[1])));
}
__device__ __forceinline__ void ld128x32(float* s, const float* g, int ld, int pad, int t){
#pragma unroll
  for(int j=0;j<4;j++){ int i4=j*256+t; int r=i4>>3, c=(i4&7)*4;
    float4 v=*(const float4*)(g + (size_t)r*ld + c);
    v.x=tf32r(v.x); v.y=tf32r(v.y); v.z=tf32r(v.z); v.w=tf32r(v.w);
    *(float4*)(s + r*pad + c)=v; }
}
__device__ __forceinline__ void ld128x16(float* s, const float* g, int ld, int pad, int t){
#pragma unroll
  for(int j=0;j<2;j++){ int i4=j*256+t; int r=i4>>2, c=(i4&3)*4;
    float4 v=*(const float4*)(g + (size_t)r*ld + c);
    v.x=tf32r(v.x); v.y=tf32r(v.y); v.z=tf32r(v.z); v.w=tf32r(v.w);
    *(float4*)(s + r*pad + c)=v; }
}
__device__ __forceinline__ void ld32x128(float* s, const float* g, int ld, int pad, int t){
#pragma unroll
  for(int j=0;j<4;j++){ int i4=j*256+t; int r=i4>>5, c=(i4&31)*4;
    float4 v=*(const float4*)(g + (size_t)r*ld + c);
    v.x=tf32r(v.x); v.y=tf32r(v.y); v.z=tf32r(v.z); v.w=tf32r(v.w);
    *(float4*)(s + r*pad + c)=v; }
}

// ---- K_q: g_Q = sigmoid(q1@W1 + q2@W2 + last@WL[0:128] + load*WL[128] + left*WL[129])
__global__ void __launch_bounds__(256,1) k_q(
 const float* __restrict__ q1,const float* __restrict__ q2,const float* __restrict__ ql,
 const float* __restrict__ load,const float* __restrict__ left,
 const float* __restrict__ W1,const float* __restrict__ W2,const float* __restrict__ WL){
 __shared__ float sA[128*36], sB[32*136];
 int t=threadIdx.x, lane=t&31, w=t>>5, wm=w>>2, wn=w&3, g=lane>>2, t4=lane&3;
 int b=blockIdx.y, p0=blockIdx.x*128;
 float acc[4][4][4]={};
 const float* srcs[3]={q1,q2,ql};
 const float* Ws[3]={W1,W2,WL};
 for(int c=0;c<12;c++){
   int s=c>>2, kc=(c&3)*32;
   __syncthreads();
   ld128x32(sA, srcs[s] + ((size_t)(b*1024+p0))*128 + kc, 128, 36, t);
   ld32x128(sB, Ws[s] + (size_t)kc*128, 128, 136, t);
   __syncthreads();
#pragma unroll
   for(int kk=0;kk<32;kk+=8){
     float a[4][4], bb[4][2];
#pragma unroll
     for(int mi=0;mi<4;mi++){ int r=(wm*64+mi*16+g)*36+kk+t4;
       a[mi][0]=sA[r]; a[mi][1]=sA[r+8*36]; a[mi][2]=sA[r+4]; a[mi][3]=sA[r+8*36+4]; }
#pragma unroll
     for(int ni=0;ni<4;ni++){ int cc=wn*32+ni*8+g;
       bb[ni][0]=sB[(kk+t4)*136+cc]; bb[ni][1]=sB[(kk+4+t4)*136+cc]; }
#pragma unroll
     for(int mi=0;mi<4;mi++)
#pragma unroll
       for(int ni=0;ni<4;ni++) mma8(acc[mi][ni], a[mi], bb[ni]);
   }
 }
#pragma unroll
 for(int mi=0;mi<4;mi++)
#pragma unroll
  for(int half=0;half<2;half++){
   int r=wm*64+mi*16+g+half*8;
   size_t pr=(size_t)(b*1024+p0+r);
   float ld=load[pr], lf=left[pr];
#pragma unroll
   for(int ni=0;ni<4;ni++){
     int h=wn*32+ni*8+t4*2;
     float v0=acc[mi][ni][half*2+0]+ld*WL[128*128+h]  +lf*WL[129*128+h];
     float v1=acc[mi][ni][half*2+1]+ld*WL[128*128+h+1]+lf*WL[129*128+h+1];
     float2 o; o.x=1.f/(1.f+__expf(-v0)); o.y=1.f/(1.f+__expf(-v1));
     *(float2*)&g_Q[pr*128+h]=o;
   }
  }
}

// ---- K_kv (fused): g_G[bn][2h]=tf32(exp(k)), [2h+1]=tf32(exp(k)*v)
__global__ void __launch_bounds__(256,1) k_kv(const float* __restrict__ nodes,
 const float* __restrict__ Wk,const float* __restrict__ Wv){
 __shared__ float sA[128*20], sB[16*264];
 int t=threadIdx.x, lane=t&31, w=t>>5, wm=w>>2, wn=w&3, g=lane>>2, t4=lane&3;
 int b=blockIdx.y, n0=blockIdx.x*128;
 float acc[4][8][4]={};
 for(int c=0;c<8;c++){
   int kc=c*16;
   __syncthreads();
   ld128x16(sA, nodes + ((size_t)(b*1024+n0))*128 + kc, 128, 20, t);
#pragma unroll
   for(int j=0;j<4;j++){ int i4=j*256+t; int r=i4>>6, cc=(i4&63)*4;
     const float* src = (cc<128)? (Wk+(size_t)(kc+r)*128+cc) : (Wv+(size_t)(kc+r)*128+cc-128);
     float4 v=*(const float4*)src;
     v.x=tf32r(v.x); v.y=tf32r(v.y); v.z=tf32r(v.z); v.w=tf32r(v.w);
     *(float4*)(sB + r*264 + cc)=v; }
   __syncthreads();
#pragma unroll
   for(int kk=0;kk<16;kk+=8){
     float a[4][4], bb[8][2];
#pragma unroll
     for(int mi=0;mi<4;mi++){ int r=(wm*64+mi*16+g)*20+kk+t4;
       a[mi][0]=sA[r]; a[mi][1]=sA[r+8*20]; a[mi][2]=sA[r+4]; a[mi][3]=sA[r+8*20+4]; }
#pragma unroll
     for(int ni=0;ni<8;ni++){
       int cc=((ni<4)? (wn*32+ni*8) : (128+wn*32+(ni-4)*8))+g;
       bb[ni][0]=sB[(kk+t4)*264+cc]; bb[ni][1]=sB[(kk+4+t4)*264+cc]; }
#pragma unroll
     for(int mi=0;mi<4;mi++)
#pragma unroll
       for(int ni=0;ni<8;ni++) mma8(acc[mi][ni], a[mi], bb[ni]);
   }
 }
#pragma unroll
 for(int mi=0;mi<4;mi++)
#pragma unroll
  for(int half=0;half<2;half++){
   int r=wm*64+mi*16+g+half*8;
   size_t bn=(size_t)(b*1024+n0+r);
#pragma unroll
   for(int ni=0;ni<4;ni++){
     int h=wn*32+ni*8+t4*2;
     float k0=acc[mi][ni][half*2],   k1=acc[mi][ni][half*2+1];
     float v0=acc[mi][ni+4][half*2], v1=acc[mi][ni+4][half*2+1];
     float e0=__expf(k0), e1=__expf(k1);
     float4 o; o.x=tf32r(e0); o.y=tf32r(e0*v0); o.z=tf32r(e1); o.w=tf32r(e1*v1);
     *(float4*)&g_G[bn*256 + 2*h]=o;
   }
  }
}

// ---- K_aft: partial [den|num] over n-slice of 512 -> g_PD[slot]
__global__ void __launch_bounds__(256,1) k_aft(const float* __restrict__ dist,
 const float* __restrict__ mask,const float* __restrict__ ls,const float* __restrict__ aa){
 __shared__ float sW[128*20], sG[16*264];
 int t=threadIdx.x, lane=t&31, w=t>>5, wm=w>>2, wn=w&3, g=lane>>2, t4=lane&3;
 int nsl=blockIdx.x, b=blockIdx.z, p0=blockIdx.y*128;
 float lsa=ls[0]*aa[0];
 float acc[4][8][4]={};
 for(int c=nsl*32;c<nsl*32+32;c++){
   int n0c=c*16;
   __syncthreads();
   { int p=t>>1, off=(t&1)*8;
     size_t base=((size_t)(b*1024+p0+p))*1024 + n0c + off;
     float4 d0=*(const float4*)(dist+base), d1=*(const float4*)(dist+base+4);
     float4 m0=*(const float4*)(mask+base), m1=*(const float4*)(mask+base+4);
     float* sw=sW+p*20+off;
     sw[0]=tf32r(__expf(m0.x-lsa*d0.x)); sw[1]=tf32r(__expf(m0.y-lsa*d0.y));
     sw[2]=tf32r(__expf(m0.z-lsa*d0.z)); sw[3]=tf32r(__expf(m0.w-lsa*d0.w));
     sw[4]=tf32r(__expf(m1.x-lsa*d1.x)); sw[5]=tf32r(__expf(m1.y-lsa*d1.y));
     sw[6]=tf32r(__expf(m1.z-lsa*d1.z)); sw[7]=tf32r(__expf(m1.w-lsa*d1.w));
   }
#pragma unroll
   for(int j=0;j<4;j++){ int i4=j*256+t; int r=i4>>6, cc=(i4&63)*4;
     *(float4*)(sG+r*264+cc)=*(const float4*)(((const float*)g_G)+((size_t)(b*1024+n0c+r))*256+cc); }
   __syncthreads();
#pragma unroll
   for(int kk=0;kk<16;kk+=8){
     float a[4][4], bb[8][2];
#pragma unroll
     for(int mi=0;mi<4;mi++){ int r=(wm*64+mi*16+g)*20+kk+t4;
       a[mi][0]=sW[r]; a[mi][1]=sW[r+8*20]; a[mi][2]=sW[r+4]; a[mi][3]=sW[r+8*20+4]; }
#pragma unroll
     for(int ni=0;ni<8;ni++){ int cc=wn*64+ni*8+g;
       bb[ni][0]=sG[(kk+t4)*264+cc]; bb[ni][1]=sG[(kk+4+t4)*264+cc]; }
#pragma unroll
     for(int mi=0;mi<4;mi++)
#pragma unroll
       for(int ni=0;ni<8;ni++) mma8(acc[mi][ni], a[mi], bb[ni]);
   }
 }
 float* pd = g_PD + (size_t)nsl*32768*256;
#pragma unroll
 for(int mi=0;mi<4;mi++)
#pragma unroll
  for(int half=0;half<2;half++){
   int r=wm*64+mi*16+g+half*8;
   size_t row=(size_t)(b*1024+p0+r);
#pragma unroll
   for(int ni=0;ni<8;ni++){
     int cc=wn*64+ni*8+t4*2;
     float2 o; o.x=acc[mi][ni][half*2]; o.y=acc[mi][ni][half*2+1];
     *(float2*)&pd[row*256+cc]=o;
   }
  }
}

// ---- K_comb: AFT = q * (num0+num1)/(den0+den1+eps)
__global__ void k_comb(){
 size_t i=(size_t)blockIdx.x*256+threadIdx.x;   // 2,097,152 threads, 4 vals each
 const float4* p0=(const float4*)g_PD;
 const float4* p1=(const float4*)(g_PD+32768ull*256);
 float4 a=p0[i], b=p1[i];
 size_t row=i>>6; int c=(int)(i&63);
 float2 q=*(const float2*)&g_Q[row*128+c*2];
 float2 o;
 o.x=tf32r(q.x*(a.y+b.y)/((a.x+b.x)+1e-20f));
 o.y=tf32r(q.y*(a.w+b.w)/((a.z+b.z)+1e-20f));
 *(float2*)&g_AFT[row*128+c*2]=o;
}

// ---- K_score: per (b,ptile,ntile-256): out=exp(10*tanh(score/sqrtE-lsp*d)+mask), slotted row sums
__global__ void __launch_bounds__(256,1) k_score(const float* __restrict__ nodes,
 const float* __restrict__ dist,const float* __restrict__ mask,
 const float* __restrict__ ls,const float* __restrict__ pa,float* __restrict__ out){
 __shared__ float sA[128*36], sB[128*36], sSum[128];
 int t=threadIdx.x, lane=t&31, w=t>>5, wm=w>>2, wn=w&3, g=lane>>2, t4=lane&3;
 int nt=blockIdx.x, b=blockIdx.z, p0=blockIdx.y*128;
 if(t<128) sSum[t]=0.f;
 float lsp=ls[0]*pa[0];
 float rs[8]={};
 for(int nc=0;nc<2;nc++){
   int n0=nt*256+nc*128;
   float acc[4][4][4]={};
   for(int kc=0;kc<4;kc++){
     __syncthreads();
     ld128x32(sA, ((const float*)g_AFT) + ((size_t)(b*1024+p0))*128 + kc*32, 128, 36, t);
     ld128x32(sB, nodes + ((size_t)(b*1024+n0))*128 + kc*32, 128, 36, t);
     __syncthreads();
#pragma unroll
     for(int kk=0;kk<32;kk+=8){
       float a[4][4], bb[4][2];
#pragma unroll
       for(int mi=0;mi<4;mi++){ int r=(wm*64+mi*16+g)*36+kk+t4;
         a[mi][0]=sA[r]; a[mi][1]=sA[r+8*36]; a[mi][2]=sA[r+4]; a[mi][3]=sA[r+8*36+4]; }
#pragma unroll
       for(int ni=0;ni<4;ni++){ int n=(wn*32+ni*8+g)*36+kk+t4;
         bb[ni][0]=sB[n]; bb[ni][1]=sB[n+4]; }
#pragma unroll
       for(int mi=0;mi<4;mi++)
#pragma unroll
         for(int ni=0;ni<4;ni++) mma8(acc[mi][ni], a[mi], bb[ni]);
     }
   }
#pragma unroll
   for(int mi=0;mi<4;mi++)
#pragma unroll
    for(int half=0;half<2;half++){
     int r=wm*64+mi*16+g+half*8;
     size_t rb=((size_t)(b*1024+p0+r))*1024;
#pragma unroll
     for(int ni=0;ni<4;ni++){
       int n=n0+wn*32+ni*8+t4*2;
       float2 d2=*(const float2*)(dist+rb+n);
       float2 m2=*(const float2*)(mask+rb+n);
       float x0=acc[mi][ni][half*2]*INV_SQRT_E - lsp*d2.x;
       float x1=acc[mi][ni][half*2+1]*INV_SQRT_E - lsp*d2.y;
       float e0=__expf(10.f*(1.f-2.f/(__expf(2.f*x0)+1.f))+m2.x);
       float e1=__expf(10.f*(1.f-2.f/(__expf(2.f*x1)+1.f))+m2.y);
       float2 o; o.x=e0; o.y=e1;
       *(float2*)(out+rb+n)=o;
       rs[mi*2+half]+=e0+e1;
     }
    }
 }
#pragma unroll
 for(int i=0;i<8;i++){
   float v=rs[i];
   v+=__shfl_xor_sync(0xffffffffu,v,1);
   v+=__shfl_xor_sync(0xffffffffu,v,2);
   if(t4==0) atomicAdd(&sSum[wm*64+(i>>1)*16+g+(i&1)*8], v);
 }
 __syncthreads();
 if(t<128) g_psum[((size_t)(b*1024+p0+t))*4 + nt] = sSum[t];
}

// ---- K_norm: one warp per row: out /= sum(4 slots)
__global__ void __launch_bounds__(256,1) k_norm(float* __restrict__ out){
 int w=threadIdx.x>>5, lane=threadIdx.x&31;
 size_t row=(size_t)blockIdx.x*8+w;
 const float4* ps=(const float4*)g_psum;
 float4 s=ps[row];
 float inv=1.f/(s.x+s.y+s.z+s.w);
 float4* o=(float4*)(out+row*1024);
#pragma unroll
 for(int i=0;i<8;i++){
   float4 v=o[lane+i*32];
   v.x*=inv; v.y*=inv; v.z*=inv; v.w*=inv;
   o[lane+i*32]=v;
 }
}

extern "C" void kernel_launch(void* const* d_in, const int*, int, void* d_out, int){
  const float* nodes=(const float*)d_in[0];
  const float* q1  =(const float*)d_in[1];
  const float* q2  =(const float*)d_in[2];
  const float* qln =(const float*)d_in[3];
  const float* load=(const float*)d_in[4];
  const float* left=(const float*)d_in[5];
  const float* dist=(const float*)d_in[6];
  const float* ls  =(const float*)d_in[7];
  const float* mask=(const float*)d_in[8];
  const float* Wq1 =(const float*)d_in[9];
  const float* Wq2 =(const float*)d_in[10];
  const float* WqL =(const float*)d_in[11];
  const float* Wk  =(const float*)d_in[12];
  const float* Wv  =(const float*)d_in[13];
  const float* aa  =(const float*)d_in[14];
  const float* pa  =(const float*)d_in[15];
  float* out=(float*)d_out;
  k_q    <<<dim3(8,32),256>>>(q1,q2,qln,load,left,Wq1,Wq2,WqL);
  k_kv   <<<dim3(8,32),256>>>(nodes,Wk,Wv);
  k_aft  <<<dim3(2,8,32),256>>>(dist,mask,ls,aa);
  k_comb <<<8192,256>>>();
  k_score<<<dim3(4,8,32),256>>>(nodes,dist,mask,ls,pa,out);
  k_norm <<<4096,256>>>(out);
}

// round 7
// speedup vs baseline: 1.5475x; 1.3352x over previous
#include <cuda_runtime.h>
#include <cstdint>

#define INV_SQRT_E 0.08838834764831843f

__device__ float g_G [32ull*1024*256];   // interleaved: [2h]=ek, [2h+1]=ek*v
__device__ float g_Q [32ull*1024*128];   // sigmoid(q)
__device__ float g_AFT[32ull*1024*128];
__device__ float g_PD [2ull*32768*256];  // partial [den|num] interleaved, 2 n-slices
__device__ float g_psum[32768ull*4];     // per-row softmax partial sums, 4 n-slots

__device__ __forceinline__ float tf32r(float x){
  uint32_t u; asm("cvt.rna.tf32.f32 %0,%1;":"=r"(u):"f"(x)); return __uint_as_float(u);
}
__device__ __forceinline__ void mma8(float* c, const float* a, const float* b){
  asm volatile("mma.sync.aligned.m16n8k8.row.col.f32.tf32.tf32.f32 "
    "{%0,%1,%2,%3},{%4,%5,%6,%7},{%8,%9},{%0,%1,%2,%3};"
    : "+f"(c[0]),"+f"(c[1]),"+f"(c[2]),"+f"(c[3])
    : "r"(__float_as_uint(a[0])),"r"(__float_as_uint(a[1])),
      "r"(__float_as_uint(a[2])),"r"(__float_as_uint(a[3])),
      "r"(__float_as_uint(b[0])),"r"(__float_as_uint(b[1])));
}
// 64x32 -> smem
__device__ __forceinline__ void ld64x32(float* s, const float* g, int ld, int pad, int t){
#pragma unroll
  for(int j=0;j<2;j++){ int i4=j*256+t; int r=i4>>3, c=(i4&7)*4;
    float4 v=*(const float4*)(g + (size_t)r*ld + c);
    v.x=tf32r(v.x); v.y=tf32r(v.y); v.z=tf32r(v.z); v.w=tf32r(v.w);
    *(float4*)(s + r*pad + c)=v; }
}
// 64x16 -> smem
__device__ __forceinline__ void ld64x16(float* s, const float* g, int ld, int pad, int t){
  int r=t>>2, c=(t&3)*4;
  float4 v=*(const float4*)(g + (size_t)r*ld + c);
  v.x=tf32r(v.x); v.y=tf32r(v.y); v.z=tf32r(v.z); v.w=tf32r(v.w);
  *(float4*)(s + r*pad + c)=v;
}
// 256x16 -> smem
__device__ __forceinline__ void ld256x16(float* s, const float* g, int ld, int pad, int t){
#pragma unroll
  for(int j=0;j<4;j++){ int i4=j*256+t; int r=i4>>2, c=(i4&3)*4;
    float4 v=*(const float4*)(g + (size_t)r*ld + c);
    v.x=tf32r(v.x); v.y=tf32r(v.y); v.z=tf32r(v.z); v.w=tf32r(v.w);
    *(float4*)(s + r*pad + c)=v; }
}
// 32x128 -> smem
__device__ __forceinline__ void ld32x128(float* s, const float* g, int ld, int pad, int t){
#pragma unroll
  for(int j=0;j<4;j++){ int i4=j*256+t; int r=i4>>5, c=(i4&31)*4;
    float4 v=*(const float4*)(g + (size_t)r*ld + c);
    v.x=tf32r(v.x); v.y=tf32r(v.y); v.z=tf32r(v.z); v.w=tf32r(v.w);
    *(float4*)(s + r*pad + c)=v; }
}

// ---- K_q: tile 64p x 128h, warps 2m x 4n, 2 CTAs/SM
__global__ void __launch_bounds__(256,2) k_q(
 const float* __restrict__ q1,const float* __restrict__ q2,const float* __restrict__ ql,
 const float* __restrict__ load,const float* __restrict__ left,
 const float* __restrict__ W1,const float* __restrict__ W2,const float* __restrict__ WL){
 __shared__ float sA[64*36], sB[32*136];
 int t=threadIdx.x, lane=t&31, w=t>>5, wm=w>>2, wn=w&3, g=lane>>2, t4=lane&3;
 int b=blockIdx.y, p0=blockIdx.x*64;
 float acc[2][4][4]={};
 const float* srcs[3]={q1,q2,ql};
 const float* Ws[3]={W1,W2,WL};
 for(int c=0;c<12;c++){
   int s=c>>2, kc=(c&3)*32;
   __syncthreads();
   ld64x32(sA, srcs[s] + ((size_t)(b*1024+p0))*128 + kc, 128, 36, t);
   ld32x128(sB, Ws[s] + (size_t)kc*128, 128, 136, t);
   __syncthreads();
#pragma unroll
   for(int kk=0;kk<32;kk+=8){
     float a[2][4], bb[4][2];
#pragma unroll
     for(int mi=0;mi<2;mi++){ int r=(wm*32+mi*16+g)*36+kk+t4;
       a[mi][0]=sA[r]; a[mi][1]=sA[r+8*36]; a[mi][2]=sA[r+4]; a[mi][3]=sA[r+8*36+4]; }
#pragma unroll
     for(int ni=0;ni<4;ni++){ int cc=wn*32+ni*8+g;
       bb[ni][0]=sB[(kk+t4)*136+cc]; bb[ni][1]=sB[(kk+4+t4)*136+cc]; }
#pragma unroll
     for(int mi=0;mi<2;mi++)
#pragma unroll
       for(int ni=0;ni<4;ni++) mma8(acc[mi][ni], a[mi], bb[ni]);
   }
 }
#pragma unroll
 for(int mi=0;mi<2;mi++)
#pragma unroll
  for(int half=0;half<2;half++){
   int r=wm*32+mi*16+g+half*8;
   size_t pr=(size_t)(b*1024+p0+r);
   float ld=load[pr], lf=left[pr];
#pragma unroll
   for(int ni=0;ni<4;ni++){
     int h=wn*32+ni*8+t4*2;
     float v0=acc[mi][ni][half*2+0]+ld*WL[128*128+h]  +lf*WL[129*128+h];
     float v1=acc[mi][ni][half*2+1]+ld*WL[128*128+h+1]+lf*WL[129*128+h+1];
     float2 o; o.x=1.f/(1.f+__expf(-v0)); o.y=1.f/(1.f+__expf(-v1));
     *(float2*)&g_Q[pr*128+h]=o;
   }
  }
}

// ---- K_kv: tile 64n x 256([Wk|Wv]), warps 2m x 4n, pairs (h,h+128) per thread
__global__ void __launch_bounds__(256,2) k_kv(const float* __restrict__ nodes,
 const float* __restrict__ Wk,const float* __restrict__ Wv){
 __shared__ float sA[64*20], sB[16*264];
 int t=threadIdx.x, lane=t&31, w=t>>5, wm=w>>2, wn=w&3, g=lane>>2, t4=lane&3;
 int b=blockIdx.y, n0=blockIdx.x*64;
 float acc[2][8][4]={};
 for(int c=0;c<8;c++){
   int kc=c*16;
   __syncthreads();
   ld64x16(sA, nodes + ((size_t)(b*1024+n0))*128 + kc, 128, 20, t);
#pragma unroll
   for(int j=0;j<4;j++){ int i4=j*256+t; int r=i4>>6, cc=(i4&63)*4;
     const float* src = (cc<128)? (Wk+(size_t)(kc+r)*128+cc) : (Wv+(size_t)(kc+r)*128+cc-128);
     float4 v=*(const float4*)src;
     v.x=tf32r(v.x); v.y=tf32r(v.y); v.z=tf32r(v.z); v.w=tf32r(v.w);
     *(float4*)(sB + r*264 + cc)=v; }
   __syncthreads();
#pragma unroll
   for(int kk=0;kk<16;kk+=8){
     float a[2][4], bb[8][2];
#pragma unroll
     for(int mi=0;mi<2;mi++){ int r=(wm*32+mi*16+g)*20+kk+t4;
       a[mi][0]=sA[r]; a[mi][1]=sA[r+8*20]; a[mi][2]=sA[r+4]; a[mi][3]=sA[r+8*20+4]; }
#pragma unroll
     for(int ni=0;ni<8;ni++){
       int cc=((ni<4)? (wn*32+ni*8) : (128+wn*32+(ni-4)*8))+g;
       bb[ni][0]=sB[(kk+t4)*264+cc]; bb[ni][1]=sB[(kk+4+t4)*264+cc]; }
#pragma unroll
     for(int mi=0;mi<2;mi++)
#pragma unroll
       for(int ni=0;ni<8;ni++) mma8(acc[mi][ni], a[mi], bb[ni]);
   }
 }
#pragma unroll
 for(int mi=0;mi<2;mi++)
#pragma unroll
  for(int half=0;half<2;half++){
   int r=wm*32+mi*16+g+half*8;
   size_t bn=(size_t)(b*1024+n0+r);
#pragma unroll
   for(int ni=0;ni<4;ni++){
     int h=wn*32+ni*8+t4*2;
     float k0=acc[mi][ni][half*2],   k1=acc[mi][ni][half*2+1];
     float v0=acc[mi][ni+4][half*2], v1=acc[mi][ni+4][half*2+1];
     float e0=__expf(k0), e1=__expf(k1);
     float4 o; o.x=tf32r(e0); o.y=tf32r(e0*v0); o.z=tf32r(e1); o.w=tf32r(e1*v1);
     *(float4*)&g_G[bn*256 + 2*h]=o;
   }
  }
}

// ---- K_aft: tile 64p x 256 G-cols, n-slice of 512, warps 2m x 4n
__global__ void __launch_bounds__(256,2) k_aft(const float* __restrict__ dist,
 const float* __restrict__ mask,const float* __restrict__ ls,const float* __restrict__ aa){
 __shared__ float sW[64*20], sG[16*264];
 int t=threadIdx.x, lane=t&31, w=t>>5, wm=w>>2, wn=w&3, g=lane>>2, t4=lane&3;
 int nsl=blockIdx.x, b=blockIdx.z, p0=blockIdx.y*64;
 float lsa=ls[0]*aa[0];
 float acc[2][8][4]={};
 for(int c=nsl*32;c<nsl*32+32;c++){
   int n0c=c*16;
   __syncthreads();
   { int p=t>>2, off=(t&3)*4;
     size_t base=((size_t)(b*1024+p0+p))*1024 + n0c + off;
     float4 d0=*(const float4*)(dist+base);
     float4 m0=*(const float4*)(mask+base);
     float* sw=sW+p*20+off;
     sw[0]=tf32r(__expf(m0.x-lsa*d0.x)); sw[1]=tf32r(__expf(m0.y-lsa*d0.y));
     sw[2]=tf32r(__expf(m0.z-lsa*d0.z)); sw[3]=tf32r(__expf(m0.w-lsa*d0.w));
   }
#pragma unroll
   for(int j=0;j<4;j++){ int i4=j*256+t; int r=i4>>6, cc=(i4&63)*4;
     *(float4*)(sG+r*264+cc)=*(const float4*)(((const float*)g_G)+((size_t)(b*1024+n0c+r))*256+cc); }
   __syncthreads();
#pragma unroll
   for(int kk=0;kk<16;kk+=8){
     float a[2][4], bb[8][2];
#pragma unroll
     for(int mi=0;mi<2;mi++){ int r=(wm*32+mi*16+g)*20+kk+t4;
       a[mi][0]=sW[r]; a[mi][1]=sW[r+8*20]; a[mi][2]=sW[r+4]; a[mi][3]=sW[r+8*20+4]; }
#pragma unroll
     for(int ni=0;ni<8;ni++){ int cc=wn*64+ni*8+g;
       bb[ni][0]=sG[(kk+t4)*264+cc]; bb[ni][1]=sG[(kk+4+t4)*264+cc]; }
#pragma unroll
     for(int mi=0;mi<2;mi++)
#pragma unroll
       for(int ni=0;ni<8;ni++) mma8(acc[mi][ni], a[mi], bb[ni]);
   }
 }
 float* pd = g_PD + (size_t)nsl*32768*256;
#pragma unroll
 for(int mi=0;mi<2;mi++)
#pragma unroll
  for(int half=0;half<2;half++){
   int r=wm*32+mi*16+g+half*8;
   size_t row=(size_t)(b*1024+p0+r);
#pragma unroll
   for(int ni=0;ni<8;ni++){
     int cc=wn*64+ni*8+t4*2;
     float2 o; o.x=acc[mi][ni][half*2]; o.y=acc[mi][ni][half*2+1];
     *(float2*)&pd[row*256+cc]=o;
   }
  }
}

// ---- K_comb: AFT = q * (num0+num1)/(den0+den1+eps)
__global__ void k_comb(){
 size_t i=(size_t)blockIdx.x*256+threadIdx.x;
 const float4* p0=(const float4*)g_PD;
 const float4* p1=(const float4*)(g_PD+32768ull*256);
 float4 a=p0[i], b=p1[i];
 size_t row=i>>6; int c=(int)(i&63);
 float2 q=*(const float2*)&g_Q[row*128+c*2];
 float2 o;
 o.x=tf32r(q.x*(a.y+b.y)/((a.x+b.x)+1e-20f));
 o.y=tf32r(q.y*(a.w+b.w)/((a.z+b.z)+1e-20f));
 *(float2*)&g_AFT[row*128+c*2]=o;
}

// ---- K_score: tile 64p x 256n, warps 2m x 4n, slotted row sums
__global__ void __launch_bounds__(256,2) k_score(const float* __restrict__ nodes,
 const float* __restrict__ dist,const float* __restrict__ mask,
 const float* __restrict__ ls,const float* __restrict__ pa,float* __restrict__ out){
 __shared__ float sA[64*20], sB[256*20], sSum[64];
 int t=threadIdx.x, lane=t&31, w=t>>5, wm=w>>2, wn=w&3, g=lane>>2, t4=lane&3;
 int nt=blockIdx.x, b=blockIdx.z, p0=blockIdx.y*64;
 int n0=nt*256;
 if(t<64) sSum[t]=0.f;
 float lsp=ls[0]*pa[0];
 float acc[2][8][4]={};
 for(int kc=0;kc<8;kc++){
   __syncthreads();
   ld64x16 (sA, ((const float*)g_AFT) + ((size_t)(b*1024+p0))*128 + kc*16, 128, 20, t);
   ld256x16(sB, nodes + ((size_t)(b*1024+n0))*128 + kc*16, 128, 20, t);
   __syncthreads();
#pragma unroll
   for(int kk=0;kk<16;kk+=8){
     float a[2][4], bb[8][2];
#pragma unroll
     for(int mi=0;mi<2;mi++){ int r=(wm*32+mi*16+g)*20+kk+t4;
       a[mi][0]=sA[r]; a[mi][1]=sA[r+8*20]; a[mi][2]=sA[r+4]; a[mi][3]=sA[r+8*20+4]; }
#pragma unroll
     for(int ni=0;ni<8;ni++){ int n=(wn*64+ni*8+g)*20+kk+t4;
       bb[ni][0]=sB[n]; bb[ni][1]=sB[n+4]; }
#pragma unroll
     for(int mi=0;mi<2;mi++)
#pragma unroll
       for(int ni=0;ni<8;ni++) mma8(acc[mi][ni], a[mi], bb[ni]);
   }
 }
 float rs[4]={};
#pragma unroll
 for(int mi=0;mi<2;mi++)
#pragma unroll
  for(int half=0;half<2;half++){
   int r=wm*32+mi*16+g+half*8;
   size_t rb=((size_t)(b*1024+p0+r))*1024;
#pragma unroll
   for(int ni=0;ni<8;ni++){
     int n=n0+wn*64+ni*8+t4*2;
     float2 d2=*(const float2*)(dist+rb+n);
     float2 m2=*(const float2*)(mask+rb+n);
     float x0=acc[mi][ni][half*2]*INV_SQRT_E - lsp*d2.x;
     float x1=acc[mi][ni][half*2+1]*INV_SQRT_E - lsp*d2.y;
     float e0=__expf(10.f*(1.f-2.f/(__expf(2.f*x0)+1.f))+m2.x);
     float e1=__expf(10.f*(1.f-2.f/(__expf(2.f*x1)+1.f))+m2.y);
     float2 o; o.x=e0; o.y=e1;
     *(float2*)(out+rb+n)=o;
     rs[mi*2+half]+=e0+e1;
   }
  }
#pragma unroll
 for(int i=0;i<4;i++){
   float v=rs[i];
   v+=__shfl_xor_sync(0xffffffffu,v,1);
   v+=__shfl_xor_sync(0xffffffffu,v,2);
   if(t4==0) atomicAdd(&sSum[wm*32+(i>>1)*16+g+(i&1)*8], v);
 }
 __syncthreads();
 if(t<64) g_psum[((size_t)(b*1024+p0+t))*4 + nt] = sSum[t];
}

// ---- K_norm: one warp per row: out /= sum(4 slots)
__global__ void __launch_bounds__(256,1) k_norm(float* __restrict__ out){
 int w=threadIdx.x>>5, lane=threadIdx.x&31;
 size_t row=(size_t)blockIdx.x*8+w;
 const float4* ps=(const float4*)g_psum;
 float4 s=ps[row];
 float inv=1.f/(s.x+s.y+s.z+s.w);
 float4* o=(float4*)(out+row*1024);
#pragma unroll
 for(int i=0;i<8;i++){
   float4 v=o[lane+i*32];
   v.x*=inv; v.y*=inv; v.z*=inv; v.w*=inv;
   o[lane+i*32]=v;
 }
}

extern "C" void kernel_launch(void* const* d_in, const int*, int, void* d_out, int){
  const float* nodes=(const float*)d_in[0];
  const float* q1  =(const float*)d_in[1];
  const float* q2  =(const float*)d_in[2];
  const float* qln =(const float*)d_in[3];
  const float* load=(const float*)d_in[4];
  const float* left=(const float*)d_in[5];
  const float* dist=(const float*)d_in[6];
  const float* ls  =(const float*)d_in[7];
  const float* mask=(const float*)d_in[8];
  const float* Wq1 =(const float*)d_in[9];
  const float* Wq2 =(const float*)d_in[10];
  const float* WqL =(const float*)d_in[11];
  const float* Wk  =(const float*)d_in[12];
  const float* Wv  =(const float*)d_in[13];
  const float* aa  =(const float*)d_in[14];
  const float* pa  =(const float*)d_in[15];
  float* out=(float*)d_out;
  k_q    <<<dim3(16,32),256>>>(q1,q2,qln,load,left,Wq1,Wq2,WqL);
  k_kv   <<<dim3(16,32),256>>>(nodes,Wk,Wv);
  k_aft  <<<dim3(2,16,32),256>>>(dist,mask,ls,aa);
  k_comb <<<8192,256>>>();
  k_score<<<dim3(4,16,32),256>>>(nodes,dist,mask,ls,pa,out);
  k_norm <<<4096,256>>>(out);
}

// round 9
// speedup vs baseline: 1.5583x; 1.0069x over previous
#include <cuda_runtime.h>
#include <cstdint>

#define INV_SQRT_E 0.08838834764831843f

__device__ float g_G [32ull*1024*256];   // interleaved: [2h]=ek, [2h+1]=ek*v
__device__ float g_Q [32ull*1024*128];   // sigmoid(q)
__device__ float g_AFT[32ull*1024*128];
__device__ float g_PD [2ull*32768*256];  // partial [den|num] interleaved, 2 n-slices
__device__ float g_psum[32768ull*8];     // per-row softmax partial sums, 8 n-slots

__device__ __forceinline__ float tf32r(float x){
  uint32_t u; asm("cvt.rna.tf32.f32 %0,%1;":"=r"(u):"f"(x)); return __uint_as_float(u);
}
__device__ __forceinline__ float4 tf32r4(float4 v){
  v.x=tf32r(v.x); v.y=tf32r(v.y); v.z=tf32r(v.z); v.w=tf32r(v.w); return v;
}
__device__ __forceinline__ void mma8(float* c, const float* a, const float* b){
  asm volatile("mma.sync.aligned.m16n8k8.row.col.f32.tf32.tf32.f32 "
    "{%0,%1,%2,%3},{%4,%5,%6,%7},{%8,%9},{%0,%1,%2,%3};"
    : "+f"(c[0]),"+f"(c[1]),"+f"(c[2]),"+f"(c[3])
    : "r"(__float_as_uint(a[0])),"r"(__float_as_uint(a[1])),
      "r"(__float_as_uint(a[2])),"r"(__float_as_uint(a[3])),
      "r"(__float_as_uint(b[0])),"r"(__float_as_uint(b[1])));
}

// ---- K_q: tile 64p x 128h, k-chunks of 16 over 3 sources (24 chunks), ping-pong
__global__ void __launch_bounds__(256,2) k_q(
 const float* __restrict__ q1,const float* __restrict__ q2,const float* __restrict__ ql,
 const float* __restrict__ load,const float* __restrict__ left,
 const float* __restrict__ W1,const float* __restrict__ W2,const float* __restrict__ WL){
 __shared__ float sA[2][64*20], sB[2][16*136];
 int t=threadIdx.x, lane=t&31, w=t>>5, wm=w>>2, wn=w&3, g=lane>>2, t4=lane&3;
 int b=blockIdx.y, p0=blockIdx.x*64;
 const float* srcs[3]={q1,q2,ql};
 const float* Ws[3]={W1,W2,WL};
 int aR=t>>2, aC=(t&3)*4;
 int bR[2], bC[2];
#pragma unroll
 for(int j=0;j<2;j++){ int i4=j*256+t; bR[j]=i4>>5; bC[j]=(i4&31)*4; }
 float acc[2][4][4]={};
 float4 rA, rB[2];
 // stage chunk 0
 rA=tf32r4(*(const float4*)(srcs[0]+((size_t)(b*1024+p0+aR))*128+aC));
#pragma unroll
 for(int j=0;j<2;j++) rB[j]=tf32r4(*(const float4*)(W1+(size_t)bR[j]*128+bC[j]));
 *(float4*)&sA[0][aR*20+aC]=rA;
#pragma unroll
 for(int j=0;j<2;j++) *(float4*)&sB[0][bR[j]*136+bC[j]]=rB[j];
 __syncthreads();
 for(int c=0;c<24;c++){
   int buf=c&1; bool more=(c+1<24);
   if(more){ int s=(c+1)>>3, kc=((c+1)&7)*16;
     rA=tf32r4(*(const float4*)(srcs[s]+((size_t)(b*1024+p0+aR))*128+kc+aC));
#pragma unroll
     for(int j=0;j<2;j++) rB[j]=tf32r4(*(const float4*)(Ws[s]+(size_t)(kc+bR[j])*128+bC[j]));
   }
   const float* cA=sA[buf]; const float* cB=sB[buf];
#pragma unroll
   for(int kk=0;kk<16;kk+=8){
     float a[2][4], bb[4][2];
#pragma unroll
     for(int mi=0;mi<2;mi++){ int r=(wm*32+mi*16+g)*20+kk+t4;
       a[mi][0]=cA[r]; a[mi][1]=cA[r+8*20]; a[mi][2]=cA[r+4]; a[mi][3]=cA[r+8*20+4]; }
#pragma unroll
     for(int ni=0;ni<4;ni++){ int cc=wn*32+ni*8+g;
       bb[ni][0]=cB[(kk+t4)*136+cc]; bb[ni][1]=cB[(kk+4+t4)*136+cc]; }
#pragma unroll
     for(int mi=0;mi<2;mi++)
#pragma unroll
       for(int ni=0;ni<4;ni++) mma8(acc[mi][ni], a[mi], bb[ni]);
   }
   if(more){
     *(float4*)&sA[buf^1][aR*20+aC]=rA;
#pragma unroll
     for(int j=0;j<2;j++) *(float4*)&sB[buf^1][bR[j]*136+bC[j]]=rB[j];
   }
   __syncthreads();
 }
#pragma unroll
 for(int mi=0;mi<2;mi++)
#pragma unroll
  for(int half=0;half<2;half++){
   int r=wm*32+mi*16+g+half*8;
   size_t pr=(size_t)(b*1024+p0+r);
   float ld=load[pr], lf=left[pr];
#pragma unroll
   for(int ni=0;ni<4;ni++){
     int h=wn*32+ni*8+t4*2;
     float v0=acc[mi][ni][half*2+0]+ld*WL[128*128+h]  +lf*WL[129*128+h];
     float v1=acc[mi][ni][half*2+1]+ld*WL[128*128+h+1]+lf*WL[129*128+h+1];
     float2 o; o.x=1.f/(1.f+__expf(-v0)); o.y=1.f/(1.f+__expf(-v1));
     *(float2*)&g_Q[pr*128+h]=o;
   }
  }
}

// ---- K_kv: tile 64n x 256([Wk|Wv]), 8 chunks of 16, ping-pong; pairs (h,h+128)/thread
__global__ void __launch_bounds__(256,2) k_kv(const float* __restrict__ nodes,
 const float* __restrict__ Wk,const float* __restrict__ Wv){
 __shared__ float sA[2][64*20], sB[2][16*264];
 int t=threadIdx.x, lane=t&31, w=t>>5, wm=w>>2, wn=w&3, g=lane>>2, t4=lane&3;
 int b=blockIdx.y, n0=blockIdx.x*64;
 int aR=t>>2, aC=(t&3)*4;
 int bR[4], bC[4];
#pragma unroll
 for(int j=0;j<4;j++){ int i4=j*256+t; bR[j]=i4>>6; bC[j]=(i4&63)*4; }
 float acc[2][8][4]={};
 float4 rA, rB[4];
 rA=tf32r4(*(const float4*)(nodes+((size_t)(b*1024+n0+aR))*128+aC));
#pragma unroll
 for(int j=0;j<4;j++){
   const float* src=(bC[j]<128)? (Wk+(size_t)bR[j]*128+bC[j]) : (Wv+(size_t)bR[j]*128+bC[j]-128);
   rB[j]=tf32r4(*(const float4*)src); }
 *(float4*)&sA[0][aR*20+aC]=rA;
#pragma unroll
 for(int j=0;j<4;j++) *(float4*)&sB[0][bR[j]*264+bC[j]]=rB[j];
 __syncthreads();
 for(int c=0;c<8;c++){
   int buf=c&1; bool more=(c+1<8);
   if(more){ int kc=(c+1)*16;
     rA=tf32r4(*(const float4*)(nodes+((size_t)(b*1024+n0+aR))*128+kc+aC));
#pragma unroll
     for(int j=0;j<4;j++){
       const float* src=(bC[j]<128)? (Wk+(size_t)(kc+bR[j])*128+bC[j]) : (Wv+(size_t)(kc+bR[j])*128+bC[j]-128);
       rB[j]=tf32r4(*(const float4*)src); }
   }
   const float* cA=sA[buf]; const float* cB=sB[buf];
#pragma unroll
   for(int kk=0;kk<16;kk+=8){
     float a[2][4], bb[8][2];
#pragma unroll
     for(int mi=0;mi<2;mi++){ int r=(wm*32+mi*16+g)*20+kk+t4;
       a[mi][0]=cA[r]; a[mi][1]=cA[r+8*20]; a[mi][2]=cA[r+4]; a[mi][3]=cA[r+8*20+4]; }
#pragma unroll
     for(int ni=0;ni<8;ni++){
       int cc=((ni<4)? (wn*32+ni*8) : (128+wn*32+(ni-4)*8))+g;
       bb[ni][0]=cB[(kk+t4)*264+cc]; bb[ni][1]=cB[(kk+4+t4)*264+cc]; }
#pragma unroll
     for(int mi=0;mi<2;mi++)
#pragma unroll
       for(int ni=0;ni<8;ni++) mma8(acc[mi][ni], a[mi], bb[ni]);
   }
   if(more){
     *(float4*)&sA[buf^1][aR*20+aC]=rA;
#pragma unroll
     for(int j=0;j<4;j++) *(float4*)&sB[buf^1][bR[j]*264+bC[j]]=rB[j];
   }
   __syncthreads();
 }
#pragma unroll
 for(int mi=0;mi<2;mi++)
#pragma unroll
  for(int half=0;half<2;half++){
   int r=wm*32+mi*16+g+half*8;
   size_t bn=(size_t)(b*1024+n0+r);
#pragma unroll
   for(int ni=0;ni<4;ni++){
     int h=wn*32+ni*8+t4*2;
     float k0=acc[mi][ni][half*2],   k1=acc[mi][ni][half*2+1];
     float v0=acc[mi][ni+4][half*2], v1=acc[mi][ni+4][half*2+1];
     float e0=__expf(k0), e1=__expf(k1);
     float4 o; o.x=tf32r(e0); o.y=tf32r(e0*v0); o.z=tf32r(e1); o.w=tf32r(e1*v1);
     *(float4*)&g_G[bn*256 + 2*h]=o;
   }
  }
}

// ---- K_aft: tile 64p x 256 G-cols, n-slice of 512 (32 chunks of 16), ping-pong
__global__ void __launch_bounds__(256,2) k_aft(const float* __restrict__ dist,
 const float* __restrict__ mask,const float* __restrict__ ls,const float* __restrict__ aa){
 __shared__ float sW[2][64*20], sG[2][16*264];
 int t=threadIdx.x, lane=t&31, w=t>>5, wm=w>>2, wn=w&3, g=lane>>2, t4=lane&3;
 int nsl=blockIdx.x, b=blockIdx.z, p0=blockIdx.y*64;
 float lsa=ls[0]*aa[0];
 int aR=t>>2, aC=(t&3)*4;
 int bR[4], bC[4];
#pragma unroll
 for(int j=0;j<4;j++){ int i4=j*256+t; bR[j]=i4>>6; bC[j]=(i4&63)*4; }
 float acc[2][8][4]={};
 float wv[4]; float4 rG[4];
 {
   int n0c=nsl*512;
   size_t base=((size_t)(b*1024+p0+aR))*1024 + n0c + aC;
   float4 d0=*(const float4*)(dist+base);
   float4 m0=*(const float4*)(mask+base);
   wv[0]=tf32r(__expf(m0.x-lsa*d0.x)); wv[1]=tf32r(__expf(m0.y-lsa*d0.y));
   wv[2]=tf32r(__expf(m0.z-lsa*d0.z)); wv[3]=tf32r(__expf(m0.w-lsa*d0.w));
#pragma unroll
   for(int j=0;j<4;j++) rG[j]=*(const float4*)(((const float*)g_G)+((size_t)(b*1024+n0c+bR[j]))*256+bC[j]);
 }
 *(float4*)&sW[0][aR*20+aC]=*(float4*)wv;
#pragma unroll
 for(int j=0;j<4;j++) *(float4*)&sG[0][bR[j]*264+bC[j]]=rG[j];
 __syncthreads();
 for(int c=0;c<32;c++){
   int buf=c&1; bool more=(c+1<32);
   if(more){ int n0c=nsl*512+(c+1)*16;
     size_t base=((size_t)(b*1024+p0+aR))*1024 + n0c + aC;
     float4 d0=*(const float4*)(dist+base);
     float4 m0=*(const float4*)(mask+base);
     wv[0]=tf32r(__expf(m0.x-lsa*d0.x)); wv[1]=tf32r(__expf(m0.y-lsa*d0.y));
     wv[2]=tf32r(__expf(m0.z-lsa*d0.z)); wv[3]=tf32r(__expf(m0.w-lsa*d0.w));
#pragma unroll
     for(int j=0;j<4;j++) rG[j]=*(const float4*)(((const float*)g_G)+((size_t)(b*1024+n0c+bR[j]))*256+bC[j]);
   }
   const float* cW=sW[buf]; const float* cG=sG[buf];
#pragma unroll
   for(int kk=0;kk<16;kk+=8){
     float a[2][4], bb[8][2];
#pragma unroll
     for(int mi=0;mi<2;mi++){ int r=(wm*32+mi*16+g)*20+kk+t4;
       a[mi][0]=cW[r]; a[mi][1]=cW[r+8*20]; a[mi][2]=cW[r+4]; a[mi][3]=cW[r+8*20+4]; }
#pragma unroll
     for(int ni=0;ni<8;ni++){ int cc=wn*64+ni*8+g;
       bb[ni][0]=cG[(kk+t4)*264+cc]; bb[ni][1]=cG[(kk+4+t4)*264+cc]; }
#pragma unroll
     for(int mi=0;mi<2;mi++)
#pragma unroll
       for(int ni=0;ni<8;ni++) mma8(acc[mi][ni], a[mi], bb[ni]);
   }
   if(more){
     *(float4*)&sW[buf^1][aR*20+aC]=*(float4*)wv;
#pragma unroll
     for(int j=0;j<4;j++) *(float4*)&sG[buf^1][bR[j]*264+bC[j]]=rG[j];
   }
   __syncthreads();
 }
 float* pd = g_PD + (size_t)nsl*32768*256;
#pragma unroll
 for(int mi=0;mi<2;mi++)
#pragma unroll
  for(int half=0;half<2;half++){
   int r=wm*32+mi*16+g+half*8;
   size_t row=(size_t)(b*1024+p0+r);
#pragma unroll
   for(int ni=0;ni<8;ni++){
     int cc=wn*64+ni*8+t4*2;
     float2 o; o.x=acc[mi][ni][half*2]; o.y=acc[mi][ni][half*2+1];
     *(float2*)&pd[row*256+cc]=o;
   }
  }
}

// ---- K_comb: AFT = q * (num0+num1)/(den0+den1+eps)
__global__ void k_comb(){
 size_t i=(size_t)blockIdx.x*256+threadIdx.x;
 const float4* p0=(const float4*)g_PD;
 const float4* p1=(const float4*)(g_PD+32768ull*256);
 float4 a=p0[i], b=p1[i];
 size_t row=i>>6; int c=(int)(i&63);
 float2 q=*(const float2*)&g_Q[row*128+c*2];
 float2 o;
 o.x=tf32r(q.x*(a.y+b.y)/((a.x+b.x)+1e-20f));
 o.y=tf32r(q.y*(a.w+b.w)/((a.z+b.z)+1e-20f));
 *(float2*)&g_AFT[row*128+c*2]=o;
}

// ---- K_score: tile 64p x 128n, 8 chunks of 16, ping-pong, 8-slot row sums
__global__ void __launch_bounds__(256,2) k_score(const float* __restrict__ nodes,
 const float* __restrict__ dist,const float* __restrict__ mask,
 const float* __restrict__ ls,const float* __restrict__ pa,float* __restrict__ out){
 __shared__ float sA[2][64*20], sB[2][128*20], sSum[64];
 int t=threadIdx.x, lane=t&31, w=t>>5, wm=w>>2, wn=w&3, g=lane>>2, t4=lane&3;
 int nt=blockIdx.x, b=blockIdx.z, p0=blockIdx.y*64;
 int n0=nt*128;
 if(t<64) sSum[t]=0.f;
 float lsp=ls[0]*pa[0];
 int aR=t>>2, aC=(t&3)*4;
 int bR[2], bC[2];
#pragma unroll
 for(int j=0;j<2;j++){ int i4=j*256+t; bR[j]=i4>>2; bC[j]=(i4&3)*4; }
 float acc[2][4][4]={};
 float4 rA, rB[2];
 rA=tf32r4(*(const float4*)(((const float*)g_AFT)+((size_t)(b*1024+p0+aR))*128+aC));
#pragma unroll
 for(int j=0;j<2;j++) rB[j]=tf32r4(*(const float4*)(nodes+((size_t)(b*1024+n0+bR[j]))*128+bC[j]));
 *(float4*)&sA[0][aR*20+aC]=rA;
#pragma unroll
 for(int j=0;j<2;j++) *(float4*)&sB[0][bR[j]*20+bC[j]]=rB[j];
 __syncthreads();
 for(int c=0;c<8;c++){
   int buf=c&1; bool more=(c+1<8);
   if(more){ int kc=(c+1)*16;
     rA=tf32r4(*(const float4*)(((const float*)g_AFT)+((size_t)(b*1024+p0+aR))*128+kc+aC));
#pragma unroll
     for(int j=0;j<2;j++) rB[j]=tf32r4(*(const float4*)(nodes+((size_t)(b*1024+n0+bR[j]))*128+kc+bC[j]));
   }
   const float* cA=sA[buf]; const float* cB=sB[buf];
#pragma unroll
   for(int kk=0;kk<16;kk+=8){
     float a[2][4], bb[4][2];
#pragma unroll
     for(int mi=0;mi<2;mi++){ int r=(wm*32+mi*16+g)*20+kk+t4;
       a[mi][0]=cA[r]; a[mi][1]=cA[r+8*20]; a[mi][2]=cA[r+4]; a[mi][3]=cA[r+8*20+4]; }
#pragma unroll
     for(int ni=0;ni<4;ni++){ int n=(wn*32+ni*8+g)*20+kk+t4;
       bb[ni][0]=cB[n]; bb[ni][1]=cB[n+4]; }
#pragma unroll
     for(int mi=0;mi<2;mi++)
#pragma unroll
       for(int ni=0;ni<4;ni++) mma8(acc[mi][ni], a[mi], bb[ni]);
   }
   if(more){
     *(float4*)&sA[buf^1][aR*20+aC]=rA;
#pragma unroll
     for(int j=0;j<2;j++) *(float4*)&sB[buf^1][bR[j]*20+bC[j]]=rB[j];
   }
   __syncthreads();
 }
 float rs[4]={};
#pragma unroll
 for(int mi=0;mi<2;mi++)
#pragma unroll
  for(int half=0;half<2;half++){
   int r=wm*32+mi*16+g+half*8;
   size_t rb=((size_t)(b*1024+p0+r))*1024;
#pragma unroll
   for(int ni=0;ni<4;ni++){
     int n=n0+wn*32+ni*8+t4*2;
     float2 d2=*(const float2*)(dist+rb+n);
     float2 m2=*(const float2*)(mask+rb+n);
     float x0=acc[mi][ni][half*2]*INV_SQRT_E - lsp*d2.x;
     float x1=acc[mi][ni][half*2+1]*INV_SQRT_E - lsp*d2.y;
     float e0=__expf(10.f*(1.f-2.f/(__expf(2.f*x0)+1.f))+m2.x);
     float e1=__expf(10.f*(1.f-2.f/(__expf(2.f*x1)+1.f))+m2.y);
     float2 o; o.x=e0; o.y=e1;
     *(float2*)(out+rb+n)=o;
     rs[mi*2+half]+=e0+e1;
   }
  }
#pragma unroll
 for(int i=0;i<4;i++){
   float v=rs[i];
   v+=__shfl_xor_sync(0xffffffffu,v,1);
   v+=__shfl_xor_sync(0xffffffffu,v,2);
   if(t4==0) atomicAdd(&sSum[wm*32+(i>>1)*16+g+(i&1)*8], v);
 }
 __syncthreads();
 if(t<64) g_psum[((size_t)(b*1024+p0+t))*8 + nt] = sSum[t];
}

// ---- K_norm: one warp per row: out /= sum(8 slots)
__global__ void __launch_bounds__(256,1) k_norm(float* __restrict__ out){
 int w=threadIdx.x>>5, lane=threadIdx.x&31;
 size_t row=(size_t)blockIdx.x*8+w;
 const float4* ps=(const float4*)g_psum;
 float4 s0=ps[row*2], s1=ps[row*2+1];
 float inv=1.f/(s0.x+s0.y+s0.z+s0.w+s1.x+s1.y+s1.z+s1.w);
 float4* o=(float4*)(out+row*1024);
#pragma unroll
 for(int i=0;i<8;i++){
   float4 v=o[lane+i*32];
   v.x*=inv; v.y*=inv; v.z*=inv; v.w*=inv;
   o[lane+i*32]=v;
 }
}

extern "C" void kernel_launch(void* const* d_in, const int*, int, void* d_out, int){
  const float* nodes=(const float*)d_in[0];
  const float* q1  =(const float*)d_in[1];
  const float* q2  =(const float*)d_in[2];
  const float* qln =(const float*)d_in[3];
  const float* load=(const float*)d_in[4];
  const float* left=(const float*)d_in[5];
  const float* dist=(const float*)d_in[6];
  const float* ls  =(const float*)d_in[7];
  const float* mask=(const float*)d_in[8];
  const float* Wq1 =(const float*)d_in[9];
  const float* Wq2 =(const float*)d_in[10];
  const float* WqL =(const float*)d_in[11];
  const float* Wk  =(const float*)d_in[12];
  const float* Wv  =(const float*)d_in[13];
  const float* aa  =(const float*)d_in[14];
  const float* pa  =(const float*)d_in[15];
  float* out=(float*)d_out;
  k_q    <<<dim3(16,32),256>>>(q1,q2,qln,load,left,Wq1,Wq2,WqL);
  k_kv   <<<dim3(16,32),256>>>(nodes,Wk,Wv);
  k_aft  <<<dim3(2,16,32),256>>>(dist,mask,ls,aa);
  k_comb <<<8192,256>>>();
  k_score<<<dim3(8,16,32),256>>>(nodes,dist,mask,ls,pa,out);
  k_norm <<<4096,256>>>(out);
}